// round 3
// baseline (speedup 1.0000x reference)
#include <cuda_runtime.h>
#include <math.h>

// ---------------------------------------------------------------------------
// BlipAttention: single-head attention over full C=768.
//   B=32, N=1024, C=768
//   qkv   = x @ qkv_w + qkv_b            (32768 x 2304)
//   S     = Q @ K^T / sqrt(C)            (32 x 1024 x 1024)
//   P     = softmax(S, axis=-1)
//   O     = P @ V                        stored TRANSPOSED per batch (C x N)
//   out   = reinterp(OT as (N,C)) @ proj_w + proj_b
// Scratch in __device__ globals (no allocation allowed).
// ---------------------------------------------------------------------------

__device__ float g_qkv[32u * 1024u * 2304u];     // ~302 MB
__device__ float g_scores[32u * 1024u * 1024u];  // ~134 MB
__device__ float g_ot[32u * 1024u * 768u];       // ~100 MB

// ---------------------------------------------------------------------------
// Generic fp32 SGEMM, 128x128 tile, BK=8, 256 threads, 8x8 per-thread tile.
// All problem dims here are exact multiples of the tile -> no bounds checks.
//  TRANSB: B operand is row-major [N,K] (we compute A * B^T)
//  TSTORE: store C transposed: C[n*ldc + m]  (used to fold the reshape)
//  BIAS  : add bias[n]
// ---------------------------------------------------------------------------
template <bool TRANSB, bool TSTORE, bool BIAS>
__global__ __launch_bounds__(256, 1) void sgemm128(
    const float* __restrict__ A, const float* __restrict__ Bm,
    const float* __restrict__ bias, float* __restrict__ Cm,
    int K, int lda, int ldb, int ldc, float alpha,
    long strideA, long strideB, long strideC)
{
    __shared__ float As[8][128];
    __shared__ float Bs[8][128];

    const int bz = blockIdx.z;
    A  += (long)bz * strideA;
    Bm += (long)bz * strideB;
    Cm += (long)bz * strideC;

    const int tid = threadIdx.x;
    const int tx = tid & 15;        // n direction (x8)
    const int ty = tid >> 4;        // m direction (x8)
    const int m0 = blockIdx.y * 128;
    const int n0 = blockIdx.x * 128;

    // A/B^T tile loads: one float4 per thread: row = tid>>1, k-quad = tid&1
    const int arow = tid >> 1;
    const int akq  = (tid & 1) * 4;
    // B (NN) tile loads: row k = tid>>5, col quad = (tid&31)*4
    const int bkrow = tid >> 5;
    const int bcol  = (tid & 31) * 4;

    float acc[8][8];
#pragma unroll
    for (int i = 0; i < 8; i++)
#pragma unroll
        for (int j = 0; j < 8; j++) acc[i][j] = 0.f;

    for (int k0 = 0; k0 < K; k0 += 8) {
        float4 av = *reinterpret_cast<const float4*>(
            &A[(long)(m0 + arow) * lda + k0 + akq]);
        As[akq + 0][arow] = av.x;
        As[akq + 1][arow] = av.y;
        As[akq + 2][arow] = av.z;
        As[akq + 3][arow] = av.w;

        if (TRANSB) {
            float4 bv = *reinterpret_cast<const float4*>(
                &Bm[(long)(n0 + arow) * ldb + k0 + akq]);
            Bs[akq + 0][arow] = bv.x;
            Bs[akq + 1][arow] = bv.y;
            Bs[akq + 2][arow] = bv.z;
            Bs[akq + 3][arow] = bv.w;
        } else {
            float4 bv = *reinterpret_cast<const float4*>(
                &Bm[(long)(k0 + bkrow) * ldb + n0 + bcol]);
            *reinterpret_cast<float4*>(&Bs[bkrow][bcol]) = bv;
        }
        __syncthreads();

#pragma unroll
        for (int kk = 0; kk < 8; kk++) {
            float ar[8], br[8];
#pragma unroll
            for (int i = 0; i < 8; i++) ar[i] = As[kk][ty * 8 + i];
#pragma unroll
            for (int j = 0; j < 8; j++) br[j] = Bs[kk][tx * 8 + j];
#pragma unroll
            for (int i = 0; i < 8; i++)
#pragma unroll
                for (int j = 0; j < 8; j++)
                    acc[i][j] = fmaf(ar[i], br[j], acc[i][j]);
        }
        __syncthreads();
    }

    // Epilogue
#pragma unroll
    for (int i = 0; i < 8; i++) {
        const int m = m0 + ty * 8 + i;
        if (TSTORE) {
#pragma unroll
            for (int j = 0; j < 8; j++) {
                const int n = n0 + tx * 8 + j;
                float v = acc[i][j] * alpha;
                if (BIAS) v += bias[n];
                Cm[(long)n * ldc + m] = v;
            }
        } else {
#pragma unroll
            for (int jq = 0; jq < 2; jq++) {
                const int n = n0 + tx * 8 + jq * 4;
                float4 v;
                v.x = acc[i][jq * 4 + 0] * alpha;
                v.y = acc[i][jq * 4 + 1] * alpha;
                v.z = acc[i][jq * 4 + 2] * alpha;
                v.w = acc[i][jq * 4 + 3] * alpha;
                if (BIAS) {
                    v.x += bias[n + 0];
                    v.y += bias[n + 1];
                    v.z += bias[n + 2];
                    v.w += bias[n + 3];
                }
                *reinterpret_cast<float4*>(&Cm[(long)m * ldc + n]) = v;
            }
        }
    }
}

// ---------------------------------------------------------------------------
// Row softmax, in place: 32768 rows of 1024 floats. 256 threads, 4 per thread.
// ---------------------------------------------------------------------------
__global__ __launch_bounds__(256) void softmax_rows(float* __restrict__ S)
{
    const long row = blockIdx.x;
    float4* p = reinterpret_cast<float4*>(S + row * 1024);
    const int tid = threadIdx.x;

    float4 v = p[tid];
    float m = fmaxf(fmaxf(v.x, v.y), fmaxf(v.z, v.w));
#pragma unroll
    for (int o = 16; o > 0; o >>= 1)
        m = fmaxf(m, __shfl_xor_sync(0xffffffffu, m, o));

    __shared__ float redm[8];
    __shared__ float reds[8];
    if ((tid & 31) == 0) redm[tid >> 5] = m;
    __syncthreads();
    float rm = redm[0];
#pragma unroll
    for (int i = 1; i < 8; i++) rm = fmaxf(rm, redm[i]);

    v.x = __expf(v.x - rm);
    v.y = __expf(v.y - rm);
    v.z = __expf(v.z - rm);
    v.w = __expf(v.w - rm);

    float s = v.x + v.y + v.z + v.w;
#pragma unroll
    for (int o = 16; o > 0; o >>= 1)
        s += __shfl_xor_sync(0xffffffffu, s, o);
    if ((tid & 31) == 0) reds[tid >> 5] = s;
    __syncthreads();
    float rs = 0.f;
#pragma unroll
    for (int i = 0; i < 8; i++) rs += reds[i];

    const float inv = 1.f / rs;
    v.x *= inv; v.y *= inv; v.z *= inv; v.w *= inv;
    p[tid] = v;
}

// ---------------------------------------------------------------------------
extern "C" void kernel_launch(void* const* d_in, const int* in_sizes, int n_in,
                              void* d_out, int out_size)
{
    const float* x      = (const float*)d_in[0];
    const float* qkv_w  = (const float*)d_in[1];
    const float* qkv_b  = (const float*)d_in[2];
    const float* proj_w = (const float*)d_in[3];
    const float* proj_b = (const float*)d_in[4];
    float* out = (float*)d_out;

    float *qkv, *sc, *ot;
    cudaGetSymbolAddress((void**)&qkv, g_qkv);
    cudaGetSymbolAddress((void**)&sc,  g_scores);
    cudaGetSymbolAddress((void**)&ot,  g_ot);

    const float scale = 1.0f / sqrtf(768.0f);

    // 1) QKV = X @ W + b : M=32768, N=2304, K=768 (NN + bias)
    sgemm128<false, false, true><<<dim3(2304 / 128, 32768 / 128, 1), 256>>>(
        x, qkv_w, qkv_b, qkv, 768, 768, 2304, 2304, 1.0f, 0, 0, 0);

    // 2) S = Q @ K^T * scale : per-batch M=1024, N=1024, K=768 (NT)
    sgemm128<true, false, false><<<dim3(8, 8, 32), 256>>>(
        qkv + 0, qkv + 768, nullptr, sc, 768, 2304, 2304, 1024, scale,
        1024L * 2304, 1024L * 2304, 1024L * 1024);

    // 3) softmax over rows
    softmax_rows<<<32 * 1024, 256>>>(sc);

    // 4) OT[c][n] = (P @ V)[n][c] : per-batch M=1024(tokens), N=768(chan),
    //    K=1024, transposed store folds the swapaxes+reshape
    sgemm128<false, true, false><<<dim3(768 / 128, 1024 / 128, 32), 256>>>(
        sc, qkv + 1536, nullptr, ot, 1024, 1024, 2304, 1024, 1.0f,
        1024L * 1024, 1024L * 2304, 768L * 1024);

    // 5) out = A2 @ proj_w + proj_b : M=32768, N=768, K=768 (NN + bias)
    //    A2 is the OT buffer reinterpreted row-major (N,C) — exactly the
    //    reference's swapaxes(1,2).reshape(B,N,C).
    sgemm128<false, false, true><<<dim3(768 / 128, 32768 / 128, 1), 256>>>(
        ot, proj_w, proj_b, out, 768, 768, 768, 768, 1.0f, 0, 0, 0);
}

// round 6
// speedup vs baseline: 3.1065x; 3.1065x over previous
#include <cuda_runtime.h>
#include <cuda_bf16.h>
#include <math.h>
#include <stdint.h>
#include <stddef.h>

// ===========================================================================
// BlipAttention via mma.sync (HMMA, sm_80-compatible PTX -> works with the
// harness's compute_103 PTX target). fp32 accuracy via bf16 hi/lo split:
//   D += Ahi*Bhi + Alo*Bhi + Ahi*Blo   (lo*lo ~ 2^-18, negligible)
// All GEMMs: D[m][n] = sum_k A[m][k]*B[n][k], operands K-major bf16.
// ===========================================================================

static __device__ __forceinline__ uint32_t smem_u32(const void* p) {
    uint32_t a;
    asm("{ .reg .u64 t; cvta.to.shared.u64 t, %1; cvt.u32.u64 %0, t; }"
        : "=r"(a) : "l"(p));
    return a;
}

#define CP_ASYNC(saddr, gaddr) \
    asm volatile("cp.async.cg.shared.global [%0], [%1], 16;" :: "r"(saddr), "l"(gaddr))
#define CP_COMMIT() asm volatile("cp.async.commit_group;" ::: "memory")
#define CP_WAIT(n)  asm volatile("cp.async.wait_group %0;" :: "n"(n) : "memory")

static __device__ __forceinline__ void ldm_x4(uint32_t* d, uint32_t addr) {
    asm volatile("ldmatrix.sync.aligned.m8n8.x4.shared.b16 {%0,%1,%2,%3}, [%4];"
                 : "=r"(d[0]), "=r"(d[1]), "=r"(d[2]), "=r"(d[3]) : "r"(addr));
}
static __device__ __forceinline__ void mma16816(float* c, const uint32_t* a,
                                                const uint32_t* b) {
    asm volatile(
        "mma.sync.aligned.m16n8k16.row.col.f32.bf16.bf16.f32 "
        "{%0,%1,%2,%3}, {%4,%5,%6,%7}, {%8,%9}, {%0,%1,%2,%3};"
        : "+f"(c[0]), "+f"(c[1]), "+f"(c[2]), "+f"(c[3])
        : "r"(a[0]), "r"(a[1]), "r"(a[2]), "r"(a[3]), "r"(b[0]), "r"(b[1]));
}

// ---------------------------------------------------------------------------
// Scratch: ONE pooled __device__ array with lifetime-based region reuse.
// ---------------------------------------------------------------------------
static constexpr size_t OFF_A   = 0;                          // 301,989,888
static constexpr size_t OFF_B   = 301989888;                  // 201,326,592
static constexpr size_t OFF_C   = OFF_B + 201326592;          // 100,663,296
static constexpr size_t OFF_D   = OFF_C + 100663296;          //   2,359,296
static constexpr size_t POOL_SZ = OFF_D + 2359296;            // ~578 MB

__device__ __align__(1024) char g_pool[POOL_SZ];

// ---------------------------------------------------------------------------
// HMMA GEMM: 128x128 tile per CTA, K in chunks of 64, cp.async double buffer.
// SMEM stage = Ahi|Alo|Bhi|Blo tiles, each 128 rows x 64 bf16 (128B, SW128).
// 8 warps: 4 in m, 2 in n -> warp tile 32(m) x 64(n).
// ---------------------------------------------------------------------------
static constexpr int STAGE_BYTES = 4 * 16384;            // 64 KB
static constexpr int SMEM_BYTES  = 2 * STAGE_BYTES;      // 128 KB

template <bool BIAS>
__global__ __launch_bounds__(256, 1)
void hgemm(const __nv_bfloat16* __restrict__ Ahi, const __nv_bfloat16* __restrict__ Alo,
           int lda, long sA,
           const __nv_bfloat16* __restrict__ Bhi, const __nv_bfloat16* __restrict__ Blo,
           int ldb, long sB,
           const float* __restrict__ bias,
           float* __restrict__ Cm, int ldc, long sC, int K)
{
    extern __shared__ __align__(1024) char smem[];
    const int tid  = threadIdx.x;
    const int wid  = tid >> 5;
    const int lane = tid & 31;
    const long bz  = blockIdx.z;
    const int m0 = blockIdx.y * 128;
    const int n0 = blockIdx.x * 128;
    Ahi += bz * sA; Alo += bz * sA;
    Bhi += bz * sB; Blo += bz * sB;
    Cm  += bz * sC;

    const uint32_t sbase = smem_u32(smem);

    // Loader per-thread geometry: 4 iters x (row = idx>>3, 16B chunk = idx&7)
    const int NC = K >> 6;

    // --- prefetch helper (macro-ish lambda) ---
    auto prefetch = [&](int ch, int s) {
        const uint32_t st = sbase + s * STAGE_BYTES;
        const int k0 = ch << 6;
        const char* gAh = (const char*)Ahi + ((long)m0 * lda + k0) * 2;
        const char* gAl = (const char*)Alo + ((long)m0 * lda + k0) * 2;
        const char* gBh = (const char*)Bhi + ((long)n0 * ldb + k0) * 2;
        const char* gBl = (const char*)Blo + ((long)n0 * ldb + k0) * 2;
        const long strA = (long)lda * 2;
        const long strB = (long)ldb * 2;
#pragma unroll
        for (int i = 0; i < 4; i++) {
            const int idx = tid + (i << 8);
            const int r   = idx >> 3;
            const int cb  = (idx & 7) << 4;
            const int sw  = r * 128 + (cb ^ ((r & 7) << 4));
            CP_ASYNC(st + sw,          gAh + (long)r * strA + cb);
            CP_ASYNC(st + 16384 + sw,  gAl + (long)r * strA + cb);
            CP_ASYNC(st + 32768 + sw,  gBh + (long)r * strB + cb);
            CP_ASYNC(st + 49152 + sw,  gBl + (long)r * strB + cb);
        }
        CP_COMMIT();
    };

    // Warp tiling
    const int wm = wid & 3;          // 0..3  (m)
    const int wn = wid >> 2;         // 0..1  (n)
    const int mb = wm * 32;
    const int nb = wn * 64;

    // ldmatrix lane geometry
    const int a_r  = (lane & 7) + ((lane >> 3) & 1) * 8;   // row within m16
    const int a_cb = (lane >> 4) * 16;                     // byte col within k16
    const int b_r  = (lane & 7) + ((lane >> 4) & 1) * 8;   // row within n16
    const int b_cb = ((lane >> 3) & 1) * 16;

    float acc[2][8][4];
#pragma unroll
    for (int i = 0; i < 2; i++)
#pragma unroll
        for (int j = 0; j < 8; j++)
#pragma unroll
            for (int v = 0; v < 4; v++) acc[i][j][v] = 0.f;

    prefetch(0, 0);

    for (int ch = 0; ch < NC; ch++) {
        if (ch + 1 < NC) prefetch(ch + 1, (ch + 1) & 1);
        if (ch + 1 < NC) { CP_WAIT(1); } else { CP_WAIT(0); }
        __syncthreads();

        const uint32_t st   = sbase + (ch & 1) * STAGE_BYTES;
        const uint32_t stAh = st;
        const uint32_t stAl = st + 16384;
        const uint32_t stBh = st + 32768;
        const uint32_t stBl = st + 49152;

#pragma unroll
        for (int ks = 0; ks < 4; ks++) {
            const int kcb = ks * 32;   // byte offset of k0 within 128B row

            uint32_t ah[2][4], al[2][4];
#pragma unroll
            for (int i = 0; i < 2; i++) {
                const int r  = mb + i * 16 + a_r;
                const int cb = kcb + a_cb;
                const uint32_t off = r * 128 + (cb ^ ((r & 7) << 4));
                ldm_x4(ah[i], stAh + off);
                ldm_x4(al[i], stAl + off);
            }
            uint32_t bh[8][2], bl[8][2];
#pragma unroll
            for (int jj = 0; jj < 4; jj++) {
                const int r  = nb + jj * 16 + b_r;
                const int cb = kcb + b_cb;
                const uint32_t off = r * 128 + (cb ^ ((r & 7) << 4));
                uint32_t t0[4], t1[4];
                ldm_x4(t0, stBh + off);
                ldm_x4(t1, stBl + off);
                bh[jj * 2][0] = t0[0]; bh[jj * 2][1] = t0[1];
                bh[jj * 2 + 1][0] = t0[2]; bh[jj * 2 + 1][1] = t0[3];
                bl[jj * 2][0] = t1[0]; bl[jj * 2][1] = t1[1];
                bl[jj * 2 + 1][0] = t1[2]; bl[jj * 2 + 1][1] = t1[3];
            }
#pragma unroll
            for (int i = 0; i < 2; i++)
#pragma unroll
                for (int j = 0; j < 8; j++) {
                    mma16816(acc[i][j], ah[i], bh[j]);
                    mma16816(acc[i][j], al[i], bh[j]);
                    mma16816(acc[i][j], ah[i], bl[j]);
                }
        }
        __syncthreads();
    }

    // Epilogue: direct stores. Thread lane: rows g, g+8; cols (lane&3)*2.
    const int g  = lane >> 2;
    const int cq = (lane & 3) * 2;
#pragma unroll
    for (int i = 0; i < 2; i++) {
        const int r0 = m0 + mb + i * 16 + g;
#pragma unroll
        for (int j = 0; j < 8; j++) {
            const int c = n0 + nb + j * 8 + cq;
            float bx = 0.f, by = 0.f;
            if (BIAS) { bx = bias[c]; by = bias[c + 1]; }
            float2 v0 = make_float2(acc[i][j][0] + bx, acc[i][j][1] + by);
            float2 v1 = make_float2(acc[i][j][2] + bx, acc[i][j][3] + by);
            *(float2*)&Cm[(long)r0 * ldc + c]       = v0;
            *(float2*)&Cm[(long)(r0 + 8) * ldc + c] = v1;
        }
    }
}

// ---------------------------------------------------------------------------
// fp32 -> bf16 hi/lo split (row-major passthrough, optional scale, batched)
// ---------------------------------------------------------------------------
__global__ __launch_bounds__(256) void split_kernel(
    const float* __restrict__ in, int lda, long sIn,
    __nv_bfloat16* __restrict__ hi, __nv_bfloat16* __restrict__ lo,
    int ldo, long sOut, unsigned C4, float scale)
{
    const long b = blockIdx.y;
    const unsigned idx = blockIdx.x * 256u + threadIdx.x;
    const unsigned row = idx / C4;
    const unsigned c4  = idx % C4;
    const float4 v = *(const float4*)(in + b * sIn + (long)row * lda + c4 * 4u);
    float x0 = v.x * scale, x1 = v.y * scale, x2 = v.z * scale, x3 = v.w * scale;
    __nv_bfloat16 h0 = __float2bfloat16(x0), h1 = __float2bfloat16(x1);
    __nv_bfloat16 h2 = __float2bfloat16(x2), h3 = __float2bfloat16(x3);
    __nv_bfloat16 l0 = __float2bfloat16(x0 - __bfloat162float(h0));
    __nv_bfloat16 l1 = __float2bfloat16(x1 - __bfloat162float(h1));
    __nv_bfloat16 l2 = __float2bfloat16(x2 - __bfloat162float(h2));
    __nv_bfloat16 l3 = __float2bfloat16(x3 - __bfloat162float(h3));
    const long o = b * sOut + (long)row * ldo + c4 * 4u;
    __nv_bfloat162* H = (__nv_bfloat162*)&hi[o];
    __nv_bfloat162* L = (__nv_bfloat162*)&lo[o];
    __nv_bfloat162 t;
    t.x = h0; t.y = h1; H[0] = t;
    t.x = h2; t.y = h3; H[1] = t;
    t.x = l0; t.y = l1; L[0] = t;
    t.x = l2; t.y = l3; L[1] = t;
}

// ---------------------------------------------------------------------------
// fp32 [R,C] -> transposed bf16 hi/lo [C,R] (batched), 32x32 SMEM tiles
// ---------------------------------------------------------------------------
__global__ __launch_bounds__(256) void tsplit_kernel(
    const float* __restrict__ in, int lda, long sIn,
    __nv_bfloat16* __restrict__ hi, __nv_bfloat16* __restrict__ lo,
    int ldo, long sOut)
{
    __shared__ float t[32][33];
    const long b = blockIdx.z;
    const int c0 = blockIdx.x * 32;
    const int r0 = blockIdx.y * 32;
    const int tx = threadIdx.x;       // 0..31
    const int ty = threadIdx.y;       // 0..7
    const float* ip = in + b * sIn;
#pragma unroll
    for (int j = 0; j < 4; j++)
        t[ty + j * 8][tx] = ip[(long)(r0 + ty + j * 8) * lda + c0 + tx];
    __syncthreads();
#pragma unroll
    for (int j = 0; j < 4; j++) {
        const float v = t[tx][ty + j * 8];
        const __nv_bfloat16 h = __float2bfloat16(v);
        const __nv_bfloat16 l = __float2bfloat16(v - __bfloat162float(h));
        const long o = b * sOut + (long)(c0 + ty + j * 8) * ldo + r0 + tx;
        hi[o] = h;
        lo[o] = l;
    }
}

// ---------------------------------------------------------------------------
// Row softmax, in place: 32768 rows of 1024 floats.
// ---------------------------------------------------------------------------
__global__ __launch_bounds__(256) void softmax_rows(float* __restrict__ S)
{
    const long row = blockIdx.x;
    float4* p = reinterpret_cast<float4*>(S + row * 1024);
    const int tid = threadIdx.x;

    float4 v = p[tid];
    float m = fmaxf(fmaxf(v.x, v.y), fmaxf(v.z, v.w));
#pragma unroll
    for (int o = 16; o > 0; o >>= 1)
        m = fmaxf(m, __shfl_xor_sync(0xffffffffu, m, o));

    __shared__ float redm[8];
    __shared__ float reds[8];
    if ((tid & 31) == 0) redm[tid >> 5] = m;
    __syncthreads();
    float rm = redm[0];
#pragma unroll
    for (int i = 1; i < 8; i++) rm = fmaxf(rm, redm[i]);

    v.x = __expf(v.x - rm);
    v.y = __expf(v.y - rm);
    v.z = __expf(v.z - rm);
    v.w = __expf(v.w - rm);

    float s = v.x + v.y + v.z + v.w;
#pragma unroll
    for (int o = 16; o > 0; o >>= 1)
        s += __shfl_xor_sync(0xffffffffu, s, o);
    if ((tid & 31) == 0) reds[tid >> 5] = s;
    __syncthreads();
    float rs = 0.f;
#pragma unroll
    for (int i = 0; i < 8; i++) rs += reds[i];

    const float inv = 1.f / rs;
    v.x *= inv; v.y *= inv; v.z *= inv; v.w *= inv;
    p[tid] = v;
}

// ---------------------------------------------------------------------------
extern "C" void kernel_launch(void* const* d_in, const int* in_sizes, int n_in,
                              void* d_out, int out_size)
{
    const float* x      = (const float*)d_in[0];
    const float* qkv_w  = (const float*)d_in[1];
    const float* qkv_b  = (const float*)d_in[2];
    const float* proj_w = (const float*)d_in[3];
    const float* proj_b = (const float*)d_in[4];
    float* out = (float*)d_out;

    char* pool;
    cudaGetSymbolAddress((void**)&pool, g_pool);

    // Region A: qkv -> scores + P
    float* qkv = (float*)(pool + OFF_A);
    float* sc  = (float*)(pool + OFF_A);
    __nv_bfloat16* phi = (__nv_bfloat16*)(pool + OFF_A + 134217728);
    __nv_bfloat16* plo = (__nv_bfloat16*)(pool + OFF_A + 134217728 + 67108864);

    // Region B: x+w1 -> q/k -> o + a5
    __nv_bfloat16* xhi  = (__nv_bfloat16*)(pool + OFF_B);
    __nv_bfloat16* xlo  = (__nv_bfloat16*)(pool + OFF_B + 50331648);
    __nv_bfloat16* w1hi = (__nv_bfloat16*)(pool + OFF_B + 100663296);
    __nv_bfloat16* w1lo = (__nv_bfloat16*)(pool + OFF_B + 100663296 + 3538944);
    __nv_bfloat16* qhi  = (__nv_bfloat16*)(pool + OFF_B);
    __nv_bfloat16* qlo  = (__nv_bfloat16*)(pool + OFF_B + 50331648);
    __nv_bfloat16* khi  = (__nv_bfloat16*)(pool + OFF_B + 100663296);
    __nv_bfloat16* klo  = (__nv_bfloat16*)(pool + OFF_B + 150994944);
    float*         o    = (float*)(pool + OFF_B);                      // 100,663,296 B
    __nv_bfloat16* a5hi = (__nv_bfloat16*)(pool + OFF_B + 100663296);
    __nv_bfloat16* a5lo = (__nv_bfloat16*)(pool + OFF_B + 150994944);

    // Region C: V^T
    __nv_bfloat16* vthi = (__nv_bfloat16*)(pool + OFF_C);
    __nv_bfloat16* vtlo = (__nv_bfloat16*)(pool + OFF_C + 50331648);

    // Region D: proj weight
    __nv_bfloat16* w5hi = (__nv_bfloat16*)(pool + OFF_D);
    __nv_bfloat16* w5lo = (__nv_bfloat16*)(pool + OFF_D + 1179648);

    cudaFuncSetAttribute(hgemm<true>,  cudaFuncAttributeMaxDynamicSharedMemorySize, SMEM_BYTES);
    cudaFuncSetAttribute(hgemm<false>, cudaFuncAttributeMaxDynamicSharedMemorySize, SMEM_BYTES);

    const float scale = 1.0f / sqrtf(768.0f);

    // Operand prep for GEMM1 + GEMM5 weights
    split_kernel<<<(32768u * 192u) / 256u, 256>>>(x, 768, 0, xhi, xlo, 768, 0, 192u, 1.f);
    tsplit_kernel<<<dim3(2304 / 32, 768 / 32, 1), dim3(32, 8)>>>(
        qkv_w, 2304, 0, w1hi, w1lo, 768, 0);
    tsplit_kernel<<<dim3(768 / 32, 768 / 32, 1), dim3(32, 8)>>>(
        proj_w, 768, 0, w5hi, w5lo, 768, 0);

    // 1) qkv = x @ qkv_w + b : M=32768, N=2304, K=768
    hgemm<true><<<dim3(18, 256, 1), 256, SMEM_BYTES>>>(
        xhi, xlo, 768, 0, w1hi, w1lo, 768, 0, qkv_b, qkv, 2304, 0, 768);

    // Split Q (scaled), K; transpose+split V  (qkv dead afterwards)
    split_kernel<<<dim3((1024u * 192u) / 256u, 32), 256>>>(
        qkv + 0, 2304, 2359296L, qhi, qlo, 768, 786432L, 192u, scale);
    split_kernel<<<dim3((1024u * 192u) / 256u, 32), 256>>>(
        qkv + 768, 2304, 2359296L, khi, klo, 768, 786432L, 192u, 1.f);
    tsplit_kernel<<<dim3(768 / 32, 1024 / 32, 32), dim3(32, 8)>>>(
        qkv + 1536, 2304, 2359296L, vthi, vtlo, 1024, 786432L);

    // 2) S = (Q*s) @ K^T : per-batch 1024x1024x768 (writes over dead qkv)
    hgemm<false><<<dim3(8, 8, 32), 256, SMEM_BYTES>>>(
        qhi, qlo, 768, 786432L, khi, klo, 768, 786432L, nullptr,
        sc, 1024, 1048576L, 768);

    // 3) softmax
    softmax_rows<<<32 * 1024, 256>>>(sc);

    // Split P (q/k dead afterwards)
    split_kernel<<<(32768u * 256u) / 256u, 256>>>(
        sc, 1024, 0, phi, plo, 1024, 0, 256u, 1.f);

    // 4) O = P @ V : per-batch 1024x768x1024 (B = V^T, K-major over tokens;
    //    writes over dead q region)
    hgemm<false><<<dim3(6, 8, 32), 256, SMEM_BYTES>>>(
        phi, plo, 1024, 1048576L, vthi, vtlo, 1024, 786432L, nullptr,
        o, 768, 786432L, 1024);

    // Transpose O per batch -> A5 (folds swapaxes+reshape), split
    // (writes over dead k region; reads o which does not overlap)
    tsplit_kernel<<<dim3(768 / 32, 1024 / 32, 32), dim3(32, 8)>>>(
        o, 768, 786432L, a5hi, a5lo, 1024, 786432L);

    // 5) out = A5 @ proj_w + proj_b : M=32768, N=768, K=768
    hgemm<true><<<dim3(6, 256, 1), 256, SMEM_BYTES>>>(
        a5hi, a5lo, 768, 0, w5hi, w5lo, 768, 0, proj_b, out, 768, 0, 768);
}